// round 13
// baseline (speedup 1.0000x reference)
#include <cuda_runtime.h>
#include <cmath>

#define BB 4
#define NN 2048
#define FF 128
#define HH 4
#define DD 32
#define MSPLIT 9
#define CROWS 128
#define MT 64

// ---- k_attn smem layout (byte offsets inside one buffer) ----
#define OFFH 0                     // 64 rows * 128 f32 (swizzled) = 32768 B
#define OFFE 32768                 // 64 j * 4 heads * float2      =  2048 B
#define OFFA 34816                 // 128 rows * u64 bitmask       =  1024 B
#define BUFB 35840
#define ATTN_SMEM (2 * BUFB)       // 71680 B double buffered

typedef unsigned long long ull;

// ---------------- scratch ----------------
__device__ float  g_h[BB * NN * FF];
__device__ float2 g_srcp[BB * NN * HH];   // (exp(e_src), exp(0.2 e_src))
__device__ float2 g_dstp[BB * NN * HH];   // (exp(e_dst), exp(0.2 e_dst))
__device__ ull    g_adjbit[NN * 32];      // bit j of [row][mtile]
__device__ float  g_num[MSPLIT * BB * NN * FF];
__device__ float  g_den[MSPLIT * BB * NN * HH];

// ---------------- helpers ----------------
__device__ __forceinline__ ull ffma2(ull a, ull b, ull c) {
    ull d;
    asm("fma.rn.f32x2 %0, %1, %2, %3;" : "=l"(d) : "l"(a), "l"(b), "l"(c));
    return d;
}
__device__ __forceinline__ ull mul2(ull a, ull b) {
    ull d;
    asm("mul.rn.f32x2 %0, %1, %2;" : "=l"(d) : "l"(a), "l"(b));
    return d;
}
__device__ __forceinline__ ull fadd2(ull a, ull b) {
    ull d;
    asm("add.rn.f32x2 %0, %1, %2;" : "=l"(d) : "l"(a), "l"(b));
    return d;
}
__device__ __forceinline__ ull pack2f(float lo, float hi) {
    ull d;
    asm("mov.b64 %0, {%1, %2};" : "=l"(d) : "f"(lo), "f"(hi));
    return d;
}
// max of the two f32 halves of a packed pair (movs coalesce to reg aliases)
__device__ __forceinline__ float fmax_halves(ull v) {
    float lo, hi;
    asm("mov.b64 {%0, %1}, %2;" : "=f"(lo), "=f"(hi) : "l"(v));
    return fmaxf(lo, hi);
}
// masked duplicate-pack: (bit ? w : 0) in both halves, short dependency chain
__device__ __forceinline__ ull wsel2(float w, unsigned bit) {
    ull d;
    asm("{\n\t"
        ".reg .pred p; .reg .b32 lo, hi;\n\t"
        "setp.ne.u32 p, %1, 0;\n\t"
        "selp.b32 lo, %2, 0, p;\n\t"
        "selp.b32 hi, %2, 0, p;\n\t"
        "mov.b64 %0, {lo, hi};\n\t"
        "}" : "=l"(d) : "r"(bit), "r"(__float_as_uint(w)));
    return d;
}
__device__ __forceinline__ float low_half(ull v) {
    float lo, hi;
    asm("mov.b64 {%0, %1}, %2;" : "=f"(lo), "=f"(hi) : "l"(v));
    return lo;
}
__device__ __forceinline__ unsigned int smem_u32(const void* p) {
    unsigned int a;
    asm("{ .reg .u64 t; cvta.to.shared.u64 t, %1; cvt.u32.u64 %0, t; }"
        : "=r"(a) : "l"(p));
    return a;
}
__device__ __forceinline__ void cp16(unsigned int dst, const void* src) {
    asm volatile("cp.async.cg.shared.global [%0], [%1], 16;" :: "r"(dst), "l"(src));
}
__device__ __forceinline__ void cp8(unsigned int dst, const void* src) {
    asm volatile("cp.async.ca.shared.global [%0], [%1], 8;" :: "r"(dst), "l"(src));
}
__device__ __forceinline__ void cp_commit() {
    asm volatile("cp.async.commit_group;");
}
__device__ __forceinline__ void cp_wait0() {
    asm volatile("cp.async.wait_group 0;");
}

// ---------------- Kernel A: h = x @ W^T (FFMA2) ----------------
#define A_SMEM ((128 * 132 + 64 * 132) * 4)

__global__ void __launch_bounds__(256) k_gemm(const float* __restrict__ x,
                                              const float* __restrict__ W) {
    extern __shared__ float sm[];
    float* shW = sm;
    float* shX = sm + 128 * 132;
    const int tid = threadIdx.x;
    const int row0 = blockIdx.x * 64;

    #pragma unroll
    for (int t = 0; t < 16; t++) {
        int idx = tid + t * 256;
        int o = idx >> 5, i4 = idx & 31;
        float4 v = ((const float4*)W)[o * 32 + i4];
        *((float4*)(shW + o * 132 + 4 * i4)) = v;
    }
    #pragma unroll
    for (int t = 0; t < 8; t++) {
        int idx = tid + t * 256;
        int r = idx >> 5, i4 = idx & 31;
        float4 v = ((const float4*)x)[(size_t)(row0 + r) * 32 + i4];
        *((float4*)(shX + r * 132 + 4 * i4)) = v;
    }
    __syncthreads();

    const int r = tid >> 2, c = tid & 3;
    ull acc2[32];
    #pragma unroll
    for (int k = 0; k < 32; k++) acc2[k] = 0ull;

    #pragma unroll 4
    for (int i4 = 0; i4 < 32; i4++) {
        ulonglong2 xv = *((const ulonglong2*)(shX + r * 132 + 4 * i4));
        #pragma unroll
        for (int k = 0; k < 32; k++) {
            int o = 4 * k + c;
            ulonglong2 wv = *((const ulonglong2*)(shW + o * 132 + 4 * i4));
            acc2[k] = ffma2(xv.x, wv.x, acc2[k]);
            acc2[k] = ffma2(xv.y, wv.y, acc2[k]);
        }
    }
    float* hrow = g_h + (size_t)(row0 + r) * FF;
    #pragma unroll
    for (int k = 0; k < 32; k++) {
        float lo, hi;
        asm("mov.b64 {%0, %1}, %2;" : "=f"(lo), "=f"(hi) : "l"(acc2[k]));
        hrow[4 * k + c] = lo + hi;
    }
}

// ---------------- Kernel B: edge terms -> factored exps (float2) ----------------
__global__ void __launch_bounds__(256) k_edge(const float* __restrict__ a_src,
                                              const float* __restrict__ a_dst) {
    int idx = blockIdx.x * 256 + threadIdx.x;
    if (idx >= BB * NN * HH) return;
    int h = idx & 3;
    int bn = idx >> 2;
    const float* hp = g_h + (size_t)bn * FF + h * DD;
    const float* as = a_src + h * DD;
    const float* ad = a_dst + h * DD;
    float es = 0.f, ed = 0.f;
    #pragma unroll
    for (int d = 0; d < DD; d++) {
        float v = hp[d];
        es = fmaf(v, as[d], es);
        ed = fmaf(v, ad[d], ed);
    }
    g_srcp[idx] = make_float2(expf(es), expf(0.2f * es));
    g_dstp[idx] = make_float2(expf(ed), expf(0.2f * ed));
}

// ---------------- Kernel B2: adj -> 64-bit row bitmasks ----------------
__global__ void __launch_bounds__(256) k_adjbit(const int* __restrict__ adj) {
    int w = (blockIdx.x * 256 + threadIdx.x) >> 5;   // 0..65535
    int lane = threadIdx.x & 31;
    int row = w >> 5;        // 0..2047
    int mt  = w & 31;        // 0..31
    const int* p = adj + (size_t)row * NN + mt * 64;
    unsigned b0 = __ballot_sync(0xffffffffu, p[lane] != 0);
    unsigned b1 = __ballot_sync(0xffffffffu, p[32 + lane] != 0);
    if (lane == 0)
        g_adjbit[row * 32 + mt] = (ull)b0 | ((ull)b1 << 32);
}

// ---------------- Kernel C: fused masked-softmax aggregation ----------------
// 256 threads: c = tid&7 -> head = c>>1, half = c&1; rg = tid>>3;
// row0 = n0 + 4*rg (4 rows x 16 cols per lane, 8 packed accs/row).
// Weight: w = exp(lrelu(es+ed)) = max(exp(es)exp(ed), exp(.2es)exp(.2ed)).
// sp2[r] = (exp(es_r), exp(.2 es_r)) packed; ep2 = (exp(ed_j), exp(.2 ed_j))
// loaded as one aligned 64-bit pair -> ONE mul2 per row then FMNMX of the
// halves; mask+dup-pack fused in wsel2 (setp+2 selp). den via FADD2.
__global__ void __launch_bounds__(256, 2) k_attn() {
    extern __shared__ char smc[];
    const unsigned smaddr = smem_u32(smc);

    const int tid  = threadIdx.x;
    const int c    = tid & 7;
    const int rg   = tid >> 3;
    const int head = c >> 1;
    const int half = c & 1;
    const int b    = blockIdx.y;
    const int z    = blockIdx.z;
    const int n0   = blockIdx.x * CROWS;
    const int row0 = n0 + 4 * rg;

    const int tile0 = (z < 5) ? 4 * z : 3 * z + 5;
    const int nt    = (z < 5) ? 4 : 3;

    // per-row packed source factors (exp(es), exp(.2es))
    ull sp2[4];
    #pragma unroll
    for (int r = 0; r < 4; r++) {
        float2 e = g_srcp[(size_t)(b * NN + row0 + r) * HH + head];
        sp2[r] = pack2f(e.x, e.y);
    }

    ull acc[4][8];
    #pragma unroll
    for (int r = 0; r < 4; r++)
        #pragma unroll
        for (int k = 0; k < 8; k++) acc[r][k] = 0ull;
    ull den2[4] = {0ull, 0ull, 0ull, 0ull};

    const char* hsrc = (const char*)(g_h + (size_t)b * NN * FF);
    const char* esrc = (const char*)(g_dstp + (size_t)b * NN * HH);

    // ---- prologue: tile0 -> buffer 0 ----
    {
        int m0 = tile0 * MT;
        unsigned bufa = smaddr;
        #pragma unroll
        for (int t2 = 0; t2 < 8; t2++) {
            int gidx = tid + t2 * 256;
            int j = gidx >> 5, q = gidx & 31;
            int qs = q ^ ((q >> 3) & 7);
            cp16(bufa + OFFH + (j * 32 + qs) * 16,
                 hsrc + ((size_t)(m0 + j) * 128 + q * 4) * 4);
        }
        if (tid < 128) {
            cp16(bufa + OFFE + tid * 16, esrc + (size_t)m0 * 32 + tid * 16);
            cp8(bufa + OFFA + tid * 8,
                (const char*)g_adjbit + ((size_t)(n0 + tid) * 32 + tile0) * 8);
        }
        cp_commit();
    }

    for (int t = 0; t < nt; t++) {
        const char* buf = smc + (t & 1) * BUFB;
        cp_wait0();
        __syncthreads();   // tile t visible; all warps done with other buffer

        if (t + 1 < nt) {  // prefetch tile t+1
            int m1 = (tile0 + t + 1) * MT;
            unsigned bufn = smaddr + ((t + 1) & 1) * BUFB;
            #pragma unroll
            for (int t2 = 0; t2 < 8; t2++) {
                int gidx = tid + t2 * 256;
                int j = gidx >> 5, q = gidx & 31;
                int qs = q ^ ((q >> 3) & 7);
                cp16(bufn + OFFH + (j * 32 + qs) * 16,
                     hsrc + ((size_t)(m1 + j) * 128 + q * 4) * 4);
            }
            if (tid < 128) {
                cp16(bufn + OFFE + tid * 16, esrc + (size_t)m1 * 32 + tid * 16);
                cp8(bufn + OFFA + tid * 8,
                    (const char*)g_adjbit +
                        ((size_t)(n0 + tid) * 32 + tile0 + t + 1) * 8);
            }
            cp_commit();
        }

        const char* sh_h = buf + OFFH;
        const ull* sh_e = (const ull*)(buf + OFFE);
        const uint2* sh_m = (const uint2*)(buf + OFFA);

        // running 32-bit mask words per row
        uint2 mw[4];
        #pragma unroll
        for (int r = 0; r < 4; r++) mw[r] = sh_m[4 * rg + r];

        #pragma unroll
        for (int hw = 0; hw < 2; hw++) {
            unsigned mm0 = hw ? mw[0].y : mw[0].x;
            unsigned mm1 = hw ? mw[1].y : mw[1].x;
            unsigned mm2 = hw ? mw[2].y : mw[2].x;
            unsigned mm3 = hw ? mw[3].y : mw[3].x;
            const ull* ep = sh_e + (size_t)hw * 32 * HH + head;
            const char* hp = sh_h + (size_t)hw * 32 * 512;

            #pragma unroll 4
            for (int j2 = 0; j2 < 32; j2++) {
                ull ep2 = ep[j2 * HH];

                ulonglong2 hv[4];
                #pragma unroll
                for (int s = 0; s < 4; s++) {
                    int q = 4 * c + s;
                    int qs = q ^ ((q >> 3) & 7);
                    hv[s] = *(const ulonglong2*)(hp + (size_t)j2 * 512 + qs * 16);
                }

                ull w2;
                // row 0
                w2 = wsel2(fmax_halves(mul2(sp2[0], ep2)), mm0 & 1u);
                mm0 >>= 1;
                den2[0] = fadd2(den2[0], w2);
                #pragma unroll
                for (int s = 0; s < 4; s++) {
                    acc[0][2 * s]     = ffma2(w2, hv[s].x, acc[0][2 * s]);
                    acc[0][2 * s + 1] = ffma2(w2, hv[s].y, acc[0][2 * s + 1]);
                }
                // row 1
                w2 = wsel2(fmax_halves(mul2(sp2[1], ep2)), mm1 & 1u);
                mm1 >>= 1;
                den2[1] = fadd2(den2[1], w2);
                #pragma unroll
                for (int s = 0; s < 4; s++) {
                    acc[1][2 * s]     = ffma2(w2, hv[s].x, acc[1][2 * s]);
                    acc[1][2 * s + 1] = ffma2(w2, hv[s].y, acc[1][2 * s + 1]);
                }
                // row 2
                w2 = wsel2(fmax_halves(mul2(sp2[2], ep2)), mm2 & 1u);
                mm2 >>= 1;
                den2[2] = fadd2(den2[2], w2);
                #pragma unroll
                for (int s = 0; s < 4; s++) {
                    acc[2][2 * s]     = ffma2(w2, hv[s].x, acc[2][2 * s]);
                    acc[2][2 * s + 1] = ffma2(w2, hv[s].y, acc[2][2 * s + 1]);
                }
                // row 3
                w2 = wsel2(fmax_halves(mul2(sp2[3], ep2)), mm3 & 1u);
                mm3 >>= 1;
                den2[3] = fadd2(den2[3], w2);
                #pragma unroll
                for (int s = 0; s < 4; s++) {
                    acc[3][2 * s]     = ffma2(w2, hv[s].x, acc[3][2 * s]);
                    acc[3][2 * s + 1] = ffma2(w2, hv[s].y, acc[3][2 * s + 1]);
                }
            }
        }
        __syncthreads();   // all warps done with buf before its refill
    }

    // ---- epilogue ----
    size_t obase = (size_t)z * (BB * NN * FF);
    #pragma unroll
    for (int r = 0; r < 4; r++) {
        ulonglong2* pr = (ulonglong2*)(g_num + obase +
                                       (size_t)(b * NN + row0 + r) * FF +
                                       head * 32 + half * 16);
        #pragma unroll
        for (int s = 0; s < 4; s++)
            pr[s] = make_ulonglong2(acc[r][2 * s], acc[r][2 * s + 1]);
    }
    if (half == 0) {
        size_t dbase = (size_t)z * (BB * NN * HH);
        #pragma unroll
        for (int r = 0; r < 4; r++)
            g_den[dbase + (size_t)(b * NN + row0 + r) * HH + head] = low_half(den2[r]);
    }
}

// ---------------- Kernel D: combine partials, normalize ----------------
__global__ void __launch_bounds__(256) k_combine(float* __restrict__ out) {
    int i4 = blockIdx.x * 256 + threadIdx.x;
    int bn = i4 >> 5;
    int head = (i4 >> 3) & 3;
    float sx = 0.f, sy = 0.f, sz = 0.f, sw = 0.f, den = 0.f;
    #pragma unroll
    for (int zz = 0; zz < MSPLIT; zz++) {
        float4 v = ((const float4*)(g_num + (size_t)zz * BB * NN * FF))[i4];
        sx += v.x; sy += v.y; sz += v.z; sw += v.w;
        den += g_den[(size_t)zz * BB * NN * HH + (size_t)bn * HH + head];
    }
    float inv = 1.f / den;
    ((float4*)out)[i4] = make_float4(sx * inv, sy * inv, sz * inv, sw * inv);
}

// ---------------- launch ----------------
extern "C" void kernel_launch(void* const* d_in, const int* in_sizes, int n_in,
                              void* d_out, int out_size) {
    const float* x     = (const float*)d_in[0];
    const int*   adj   = (const int*)d_in[1];
    const float* W     = (const float*)d_in[2];
    const float* a_src = (const float*)d_in[3];
    const float* a_dst = (const float*)d_in[4];
    float* out = (float*)d_out;

    cudaFuncSetAttribute(k_gemm, cudaFuncAttributeMaxDynamicSharedMemorySize, A_SMEM);
    cudaFuncSetAttribute(k_attn, cudaFuncAttributeMaxDynamicSharedMemorySize, ATTN_SMEM);

    k_adjbit<<<NN * 32 * 32 / 256, 256>>>(adj);
    k_gemm<<<(BB * NN) / 64, 256, A_SMEM>>>(x, W);
    k_edge<<<(BB * NN * HH) / 256, 256>>>(a_src, a_dst);
    dim3 gC(NN / CROWS, BB, MSPLIT);
    k_attn<<<gC, 256, ATTN_SMEM>>>();
    k_combine<<<(BB * NN * FF / 4) / 256, 256>>>(out);
}